// round 11
// baseline (speedup 1.0000x reference)
#include <cuda_runtime.h>
#include <cuda_bf16.h>
#include <cstdint>

// ---- problem constants ----
#define T1n 128
#define T2n 512
#define TPn 8
#define Hn  16
#define Kn  4
#define Cn  129   // 2*K*H+1
#define Dn  256

// ---- device scratch ----
__device__ float  g_val[T1n * T2n];
__device__ uint2  g_pack[T1n * TPn * T2n];    // bucket-sorted compacted {awb, ap}
__device__ int    g_bs[T1n * TPn * 17];       // bucket starts (bs[16] = cnt)
__device__ float2 g_WN[T1n * TPn * 16];       // per-bucket {sum aw, (float)count}
__device__ float  g_SA[T1n * TPn];            // sum m*A^2
__device__ float  g_L64[T1n];                 // loss for c == sta

// ---------------------------------------------------------------------------
// K1: val_v[i][j]. Grid (32,4): block = 4 i-rows x 128 j-cols, 512 threads.
//   Phase A: ssq prepass (4 threads/row, quad shfl) -> s_inv2; stages e2 in L1.
//   Phase B: e1 row norms -> normalized rows in smem.
//   Phase C: dot with 4 independent accumulators (chain /4), e2 from L1,
//            e1 via broadcast LDS.128.
// ---------------------------------------------------------------------------
__global__ __launch_bounds__(512) void k_val(const float* __restrict__ e1,
                                             const float* __restrict__ e2) {
    int i0 = blockIdx.x * 4;
    int j0 = blockIdx.y * 128;
    int tid = threadIdx.x;

    __shared__ float s1[4][Dn];
    __shared__ float s_red[4][4];
    __shared__ float s_inv2[128];

    // phase A: e2 row ssq (4 threads per row)
    {
        int j2 = tid >> 2, part = tid & 3;
        const float4* rp = (const float4*)(e2 + (j0 + j2) * Dn);
        float s = 0.f;
        #pragma unroll
        for (int u = 0; u < 16; u++) {
            float4 v = rp[part + 4 * u];
            s = fmaf(v.x, v.x, s); s = fmaf(v.y, v.y, s);
            s = fmaf(v.z, v.z, s); s = fmaf(v.w, v.w, s);
        }
        s += __shfl_down_sync(0xffffffffu, s, 2, 4);
        s += __shfl_down_sync(0xffffffffu, s, 1, 4);
        if (part == 0) s_inv2[j2] = rsqrtf(s);
    }

    // phase B: e1 row norms + normalized rows into smem
    int q = tid >> 7, r = tid & 127;
    {
        float a0 = e1[(i0 + q) * Dn + r];
        float a1 = e1[(i0 + q) * Dn + 128 + r];
        float ss = a0 * a0 + a1 * a1;
        for (int o = 16; o; o >>= 1) ss += __shfl_down_sync(0xffffffffu, ss, o);
        if ((r & 31) == 0) s_red[q][r >> 5] = ss;
        __syncthreads();
        float inv = rsqrtf(s_red[q][0] + s_red[q][1] + s_red[q][2] + s_red[q][3]);
        s1[q][r] = a0 * inv;
        s1[q][r + 128] = a1 * inv;
    }
    __syncthreads();

    // phase C: dot, 4 accumulators
    int j = j0 + r;
    const float4* rp = (const float4*)(e2 + j * Dn);
    const float4* ap = (const float4*)(&s1[q][0]);
    float d0 = 0.f, d1 = 0.f, d2 = 0.f, d3 = 0.f;
    #pragma unroll
    for (int k4 = 0; k4 < 64; k4 += 4) {
        float4 b0 = rp[k4],     a0 = ap[k4];
        float4 b1 = rp[k4 + 1], a1 = ap[k4 + 1];
        float4 b2 = rp[k4 + 2], a2 = ap[k4 + 2];
        float4 b3 = rp[k4 + 3], a3 = ap[k4 + 3];
        d0 = fmaf(a0.x, b0.x, d0); d0 = fmaf(a0.y, b0.y, d0);
        d0 = fmaf(a0.z, b0.z, d0); d0 = fmaf(a0.w, b0.w, d0);
        d1 = fmaf(a1.x, b1.x, d1); d1 = fmaf(a1.y, b1.y, d1);
        d1 = fmaf(a1.z, b1.z, d1); d1 = fmaf(a1.w, b1.w, d1);
        d2 = fmaf(a2.x, b2.x, d2); d2 = fmaf(a2.y, b2.y, d2);
        d2 = fmaf(a2.z, b2.z, d2); d2 = fmaf(a2.w, b2.w, d2);
        d3 = fmaf(a3.x, b3.x, d3); d3 = fmaf(a3.y, b3.y, d3);
        d3 = fmaf(a3.z, b3.z, d3); d3 = fmaf(a3.w, b3.w, d3);
    }
    float dot = (d0 + d1) + (d2 + d3);
    g_val[(i0 + q) * T2n + j] = dot * s_inv2[r];
}

// ---------------------------------------------------------------------------
// K2: build. Grid 128 (block per i); 512 threads (16 warps).
// ---------------------------------------------------------------------------
__global__ __launch_bounds__(512) void k_build(const int* __restrict__ sta,
                                               const int* __restrict__ pos,
                                               const unsigned* __restrict__ mask) {
    int i = blockIdx.x;
    int tid = threadIdx.x;
    int lane = tid & 31, w = tid >> 5;
    unsigned lt = (1u << lane) - 1u;

    __shared__ uint2 s_all[TPn][T2n];     // 32 KB
    __shared__ int   s_cm[TPn][16][16];   // [t][warp][bucket] counts -> offsets
    __shared__ int   s_bs[TPn][17];
    __shared__ int   s_st[TPn];
    __shared__ float s_red[16][9];

    if (tid < TPn) s_st[tid] = sta[i * TPn + tid];
    #pragma unroll
    for (int u = 0; u < 4; u++) ((int*)s_cm)[tid + 512 * u] = 0;
    __syncthreads();

    int j = tid;
    int4 p0 = ((const int4*)pos)[j * 2];
    int4 p1 = ((const int4*)pos)[j * 2 + 1];
    int pv[TPn] = {p0.x, p0.y, p0.z, p0.w, p1.x, p1.y, p1.z, p1.w};
    bool m = (mask[i * T2n + j] != 0u);
    float val = g_val[i * T2n + j];

    float dis[TPn];
    int   ab[TPn];
    float dsum = 0.f;
    #pragma unroll
    for (int tt = 0; tt < TPn; tt++) {
        int stt = s_st[tt];
        int a = stt < 0 ? -stt : stt;
        int b = pv[tt] < 0 ? -pv[tt] : pv[tt];
        ab[tt] = b;
        float sg = ((stt ^ pv[tt]) < 0) ? -1.0f : 1.0f;
        int v = (a ^ b) + 1;
        int p; asm("bfind.u32 %0, %1;" : "=r"(p) : "r"(v));
        float d = sg * (float)(15 - p) * (1.0f / 16.0f);
        dis[tt] = d;
        dsum += d;
    }

    // SA_t and L64 reductions
    {
        float red9[9];
        float B = dsum * 0.125f - val;
        red9[8] = m ? B * B : 0.0f;
        #pragma unroll
        for (int tt = 0; tt < TPn; tt++) {
            float A = (dsum - dis[tt]) * 0.125f - val;
            red9[tt] = m ? A * A : 0.0f;
        }
        #pragma unroll
        for (int o = 16; o; o >>= 1) {
            #pragma unroll
            for (int x = 0; x < 9; x++)
                red9[x] += __shfl_down_sync(0xffffffffu, red9[x], o);
        }
        if (lane == 0) {
            #pragma unroll
            for (int x = 0; x < 9; x++) s_red[w][x] = red9[x];
        }
    }

    // per-(t,warp,bucket) counts
    unsigned ball = __ballot_sync(0xffffffffu, m);
    int rank[TPn];
    #pragma unroll
    for (int tt = 0; tt < TPn; tt++) {
        int b = ab[tt] >> 12;
        unsigned same = __match_any_sync(0xffffffffu, b) & ball;
        rank[tt] = __popc(same & lt);
        if (m && rank[tt] == 0) s_cm[tt][w][b] = __popc(same);
    }
    __syncthreads();

    // warps 0..7 scan their t. ALL 32 lanes execute the width-16 shfl;
    // smem writes guarded by lane<16.
    if (w < TPn) {
        int t = w, b = lane & 15;
        int tot = 0;
        #pragma unroll
        for (int ww = 0; ww < 16; ww++) tot += s_cm[t][ww][b];
        int run = tot;
        #pragma unroll
        for (int o = 1; o < 16; o <<= 1) {
            int n = __shfl_up_sync(0xffffffffu, run, o, 16);
            if ((lane & 15) >= o) run += n;
        }
        if (lane < 16) {
            int excl = run - tot;
            s_bs[t][b] = excl;
            if (b == 15) s_bs[t][16] = run;
            int acc = excl;
            #pragma unroll
            for (int ww = 0; ww < 16; ww++) {
                int c = s_cm[t][ww][b]; s_cm[t][ww][b] = acc; acc += c;
            }
        }
    }
    // SA/L64 finalize
    if (tid >= 288 && tid < 297) {
        int x = tid - 288;
        float s = 0.f;
        #pragma unroll
        for (int ww = 0; ww < 16; ww++) s += s_red[ww][x];
        if (x < 8) g_SA[i * TPn + x] = s;
        else       g_L64[i] = s;
    }
    __syncthreads();

    // scatter all 8 t into smem
    if (m) {
        #pragma unroll
        for (int tt = 0; tt < TPn; tt++) {
            float A = (dsum - dis[tt]) * 0.125f - val;
            unsigned awb = __float_as_uint(A * (1.0f / 128.0f)) ^
                           ((unsigned)pv[tt] & 0x80000000u);
            int slot = s_cm[tt][w][ab[tt] >> 12] + rank[tt];
            s_all[tt][slot] = make_uint2(awb, (unsigned)ab[tt]);
        }
    }
    __syncthreads();

    // W/N per (t,b): 128 units x 4 threads
    {
        int unit = tid >> 2, q4 = tid & 3;
        int t = unit >> 4, b = unit & 15;
        int lo = s_bs[t][b], hi = s_bs[t][b + 1];
        float ws = 0.f;
        for (int k = lo + q4; k < hi; k += 4) ws += __uint_as_float(s_all[t][k].x);
        ws += __shfl_down_sync(0xffffffffu, ws, 2, 4);
        ws += __shfl_down_sync(0xffffffffu, ws, 1, 4);
        if (q4 == 0)
            g_WN[(i * TPn + t) * 16 + b] = make_float2(ws, (float)(hi - lo));
    }
    int cnt = s_bs[0][16];
    #pragma unroll
    for (int tt = 0; tt < TPn; tt++) {
        if (tid < cnt)
            g_pack[(i * TPn + tt) * T2n + tid] = s_all[tt][tid];
    }
    if (tid < TPn * 17) {
        int t = tid / 17, x = tid % 17;
        g_bs[(i * TPn + t) * 17 + x] = s_bs[t][x];
    }
}

// ---------------------------------------------------------------------------
// K3: loss. Grid (i,t) = (128,8); 256 threads; 4 threads per candidate.
// ---------------------------------------------------------------------------
__device__ __forceinline__ int make_cand(int c, int stav, const int* rm, int i, int t) {
    int h = c >> 2, k = c & 3;
    int r = rm[((i * Hn + h) * Kn + k) * TPn + t];
    return (stav ^ (1 << h)) ^ (r & ((1 << h) - 1));
}

__global__ __launch_bounds__(256, 6) void k_loss(const int* __restrict__ sta,
                                                 const int* __restrict__ rmask,
                                                 float* __restrict__ out) {
    int i = blockIdx.x, t = blockIdx.y;
    int tid = threadIdx.x;

    __shared__ uint2    s_pk[T2n];       // 4 KB
    __shared__ unsigned s_bm[2048];      // 8 KB presence bitmap over ap
    __shared__ int      s_bs[17];
    __shared__ float2   s_WN[16];

    int base = (i * TPn + t);
    if (tid < 17) s_bs[tid] = g_bs[base * 17 + tid];
    else if (tid >= 32 && tid < 48) s_WN[tid - 32] = g_WN[base * 16 + tid - 32];
    #pragma unroll
    for (int u = 0; u < 8; u++) s_bm[tid + 256 * u] = 0u;
    int cnt = __ldg(&g_bs[base * 17 + 16]);
    __syncthreads();

    const uint2* gp = g_pack + base * T2n;
    for (int idx = tid; idx < cnt; idx += 256) {
        uint2 e = gp[idx];
        s_pk[idx] = e;
        atomicOr(&s_bm[e.y >> 5], 1u << (e.y & 31));
    }
    __syncthreads();

    int c  = tid >> 2;                  // 0..63
    int q4 = tid & 3;
    int stav = sta[i * TPn + t];
    int cand = make_cand(c, stav, rmask, i, t);
    unsigned ac = (unsigned)(cand < 0 ? -cand : cand);
    int acH = (int)(ac >> 12);          // 0..16

    float S2 = 0.f, Sq = 0.f;

    // (a) bucket aggregates: 4 buckets per thread
    #pragma unroll
    for (int u = 0; u < 4; u++) {
        int b = q4 * 4 + u;
        if (b != acH) {
            int xh = acH ^ b;                               // 1..31
            int mb; asm("bfind.u32 %0, %1;" : "=r"(mb) : "r"(xh));
            float f = 8388611.0f - __int_as_float(mb | 0x4B000000);   // 3 - mb
            float2 wn = s_WN[b];
            S2 = fmaf(wn.x, f, S2);
            Sq = fmaf(wn.y, f * f, Sq);
        }
    }

    // (b) exact scan of matching bucket
    if (acH < 16) {
        int hi = s_bs[acH + 1];
        for (int k = s_bs[acH] + q4; k < hi; k += 4) {
            uint2 e = s_pk[k];
            unsigned v = (ac ^ e.y) + 1u;
            int qq; asm("bfind.u32 %0, %1;" : "=r"(qq) : "r"(v));
            float f = 8388623.0f - __int_as_float(qq | 0x4B000000);   // 15 - qq
            S2 = fmaf(__uint_as_float(e.x), f, S2);
            Sq = fmaf(f, f, Sq);
        }
    }

    // (c) ripple fixups: k = 13+q4; q4==0 also handles k=17
    #pragma unroll
    for (int pp = 0; pp < 2; pp++) {
        int kk = (pp == 0) ? (13 + q4) : 17;
        if (pp == 1 && q4 != 0) break;
        unsigned rv = ac ^ ((1u << kk) - 1u);
        if (rv <= 65535u) {
            if (s_bm[rv >> 5] & (1u << (rv & 31))) {
                int bb = (int)(rv >> 12);
                int lo = s_bs[bb], hi = s_bs[bb + 1];
                float dq = (float)(2 * kk - 31);
                for (int k = lo; k < hi; k++) {
                    uint2 e = s_pk[k];
                    if (e.y == rv) { S2 -= __uint_as_float(e.x); Sq += dq; }
                }
            }
        }
    }

    // quad reduce
    S2 += __shfl_down_sync(0xffffffffu, S2, 2, 4);
    S2 += __shfl_down_sync(0xffffffffu, S2, 1, 4);
    Sq += __shfl_down_sync(0xffffffffu, Sq, 2, 4);
    Sq += __shfl_down_sync(0xffffffffu, Sq, 1, 4);

    if (q4 == 0) {
        float SA = g_SA[base];
        float bse = SA + Sq * (1.0f / 16384.0f);
        float sc  = cand < 0 ? -1.0f : 1.0f;
        float tw  = 2.0f * sc * S2;
        float lp  = bse + tw;
        out[(i * Cn + c) * TPn + t] = lp;
        out[(i * Cn + 65 + c) * TPn + t] = (cand == 0) ? lp : (bse - tw);
    }
    if (tid == 0)
        out[(i * Cn + 64) * TPn + t] = g_L64[i];
}

// ---------------------------------------------------------------------------
extern "C" void kernel_launch(void* const* d_in, const int* in_sizes, int n_in,
                              void* d_out, int out_size) {
    const float*    emb1 = (const float*)d_in[0];
    const float*    emb2 = (const float*)d_in[1];
    const int*      sta  = (const int*)d_in[2];
    const int*      pos  = (const int*)d_in[3];
    const unsigned* mask = (const unsigned*)d_in[4];
    const int*      rm   = (const int*)d_in[5];
    float*          out  = (float*)d_out;

    k_val<<<dim3(32, 4), 512>>>(emb1, emb2);
    k_build<<<T1n, 512>>>(sta, pos, mask);
    k_loss<<<dim3(T1n, TPn), 256>>>(sta, rm, out);
}